// round 1
// baseline (speedup 1.0000x reference)
#include <cuda_runtime.h>
#include <cstdint>

// Problem constants
#define E_DIM 256
#define I_DIM 35
#define C_DIM 64
#define K_SCALAR 105          // 3*I scalar features
#define EMB_ROW0 106          // emb rows start here (row 105 = zero pad)
#define KROWS 246             // 106 + 35*4
#define TILE_B 32
#define THREADS_MAIN 256

// Scratch (device globals: no allocation allowed)
__device__ float g_W2T[KROWS * E_DIM];     // [row][e] folded weight matrix
__device__ float g_Bsum[I_DIM * E_DIM];    // per-i bias dot partials
__device__ float g_const[E_DIM];           // bf + all bias contributions

// ---------------- f32x2 helpers ----------------
__device__ __forceinline__ void fma2(unsigned long long& d, unsigned long long a, unsigned long long b) {
    asm("fma.rn.f32x2 %0, %1, %2, %0;" : "+l"(d) : "l"(a), "l"(b));
}
__device__ __forceinline__ void add2(unsigned long long& d, unsigned long long a) {
    asm("add.rn.f32x2 %0, %0, %1;" : "+l"(d) : "l"(a));
}
__device__ __forceinline__ unsigned long long pk2(float a, float b) {
    unsigned long long r; asm("mov.b64 %0, {%1, %2};" : "=l"(r) : "f"(a), "f"(b)); return r;
}
__device__ __forceinline__ void upk2(unsigned long long v, float& a, float& b) {
    asm("mov.b64 {%0, %1}, %2;" : "=f"(a), "=f"(b) : "l"(v));
}

// ---------------- Precompute: fold Wf with per-feature weight vectors ----------------
// One warp per (e, i): 7 dots of length C=64 + combined bias dot.
__global__ void precompute_kernel(const float* __restrict__ Wd, const float* __restrict__ bd,
                                  const float* __restrict__ Wc, const float* __restrict__ bc,
                                  const float* __restrict__ Wr, const float* __restrict__ br,
                                  const float* __restrict__ emb, const float* __restrict__ Wf) {
    int gw = (blockIdx.x * blockDim.x + threadIdx.x) >> 5;
    int lane = threadIdx.x & 31;
    if (gw >= E_DIM * I_DIM) return;
    int e = gw / I_DIM;
    int i = gw - e * I_DIM;
    const float* wf = Wf + (size_t)e * (I_DIM * 4 * C_DIM) + (size_t)i * (4 * C_DIM);

    float pd = 0.f, pc = 0.f, pr = 0.f, pb = 0.f;
    float pe0 = 0.f, pe1 = 0.f, pe2 = 0.f, pe3 = 0.f;
    #pragma unroll
    for (int cc = 0; cc < 2; cc++) {
        int c = lane + cc * 32;
        float f0 = wf[c];
        float f1 = wf[C_DIM + c];
        float f2 = wf[2 * C_DIM + c];
        float f3 = wf[3 * C_DIM + c];
        pd += Wd[i * C_DIM + c] * f0;  pb += bd[i * C_DIM + c] * f0;
        pc += Wc[i * C_DIM + c] * f1;  pb += bc[i * C_DIM + c] * f1;
        pr += Wr[i * C_DIM + c] * f2;  pb += br[i * C_DIM + c] * f2;
        pe0 += emb[(i * 4 + 0) * C_DIM + c] * f3;
        pe1 += emb[(i * 4 + 1) * C_DIM + c] * f3;
        pe2 += emb[(i * 4 + 2) * C_DIM + c] * f3;
        pe3 += emb[(i * 4 + 3) * C_DIM + c] * f3;
    }
    #pragma unroll
    for (int o = 16; o; o >>= 1) {
        pd  += __shfl_down_sync(0xffffffffu, pd, o);
        pc  += __shfl_down_sync(0xffffffffu, pc, o);
        pr  += __shfl_down_sync(0xffffffffu, pr, o);
        pb  += __shfl_down_sync(0xffffffffu, pb, o);
        pe0 += __shfl_down_sync(0xffffffffu, pe0, o);
        pe1 += __shfl_down_sync(0xffffffffu, pe1, o);
        pe2 += __shfl_down_sync(0xffffffffu, pe2, o);
        pe3 += __shfl_down_sync(0xffffffffu, pe3, o);
    }
    if (lane == 0) {
        g_W2T[(0 * I_DIM + i) * E_DIM + e] = pd;
        g_W2T[(1 * I_DIM + i) * E_DIM + e] = pc;
        g_W2T[(2 * I_DIM + i) * E_DIM + e] = pr;
        g_W2T[(EMB_ROW0 + 4 * i + 0) * E_DIM + e] = pe0;
        g_W2T[(EMB_ROW0 + 4 * i + 1) * E_DIM + e] = pe1;
        g_W2T[(EMB_ROW0 + 4 * i + 2) * E_DIM + e] = pe2;
        g_W2T[(EMB_ROW0 + 4 * i + 3) * E_DIM + e] = pe3;
        g_Bsum[i * E_DIM + e] = pb;
    }
}

__global__ void finalize_kernel(const float* __restrict__ bf) {
    int e = threadIdx.x;
    float s = bf[e];
    #pragma unroll
    for (int i = 0; i < I_DIM; i++) s += g_Bsum[i * E_DIM + e];
    g_const[e] = s;
    g_W2T[K_SCALAR * E_DIM + e] = 0.0f;   // zero pad row 105 (paired with X pad)
}

// ---------------- Main: out[b,e] = relu(LN(const + X·W2T + emb gathers)) ----------------
// Block: 32 samples x full E=256. Thread: 8 samples x 4 e (two f32x2 accum pairs per j).
__global__ __launch_bounds__(THREADS_MAIN)
void main_kernel(const float* __restrict__ metadata,
                 const float* __restrict__ gamma,
                 const float* __restrict__ beta,
                 float* __restrict__ out) {
    __shared__ __align__(16) float2 Xs2[TILE_B * 106];   // pre-duplicated {x,x}, pad k=105
    __shared__ int offs[TILE_B * 36];                    // emb row offsets (floats)
    __shared__ float red[8][8][2];                       // [warp][j][{s1,s2}]

    const int tid = threadIdx.x;
    const int b0 = blockIdx.x * TILE_B;

    // Stage X scalars, duplicated for f32x2
    for (int idx = tid; idx < TILE_B * K_SCALAR; idx += THREADS_MAIN) {
        int j = idx / K_SCALAR;
        int k = idx - j * K_SCALAR;
        float v = metadata[(size_t)(b0 + j) * 140 + k];
        Xs2[j * 106 + k] = make_float2(v, v);
    }
    if (tid < TILE_B) Xs2[tid * 106 + K_SCALAR] = make_float2(0.f, 0.f);

    // Stage rt -> W2T row byte offsets
    for (int idx = tid; idx < TILE_B * I_DIM; idx += THREADS_MAIN) {
        int j = idx / I_DIM;
        int i = idx - j * I_DIM;
        float v = metadata[(size_t)(b0 + j) * 140 + K_SCALAR + i];
        int ri = (int)v;
        int r = ri >= 0 ? ri : (ri == -1 ? 2 : 3);
        offs[j * 36 + i] = (EMB_ROW0 + 4 * i + r) * E_DIM;
    }
    __syncthreads();

    const int eq = tid & 63;          // 64 e-quads
    const int jg = tid >> 6;          // 4 sample groups of 8
    const int e0 = eq * 4;
    const int jbase = jg * 8;

    const ulonglong2* __restrict__ W64 = reinterpret_cast<const ulonglong2*>(g_W2T);

    // acc init from const[e]
    float4 cv = *reinterpret_cast<const float4*>(&g_const[e0]);
    unsigned long long c_lo = pk2(cv.x, cv.y);
    unsigned long long c_hi = pk2(cv.z, cv.w);
    unsigned long long acc[8][2];
    #pragma unroll
    for (int j = 0; j < 8; j++) { acc[j][0] = c_lo; acc[j][1] = c_hi; }

    // Scalar feature GEMM: 53 k-pairs (k=0..105, 105 is zero pad)
    #pragma unroll 1
    for (int kp = 0; kp < 53; kp++) {
        int k = kp * 2;
        ulonglong2 w0 = W64[(k * E_DIM + e0) >> 2];
        ulonglong2 w1 = W64[((k + 1) * E_DIM + e0) >> 2];
        #pragma unroll
        for (int j = 0; j < 8; j++) {
            ulonglong2 xx = *reinterpret_cast<const ulonglong2*>(&Xs2[(jbase + j) * 106 + k]);
            fma2(acc[j][0], xx.x, w0.x);
            fma2(acc[j][1], xx.x, w0.y);
            fma2(acc[j][0], xx.y, w1.x);
            fma2(acc[j][1], xx.y, w1.y);
        }
    }

    // Embedding gathers: 35 adds of gathered W2T rows
    #pragma unroll 1
    for (int i = 0; i < I_DIM; i++) {
        #pragma unroll
        for (int j = 0; j < 8; j++) {
            int off = offs[(jbase + j) * 36 + i];
            ulonglong2 w = W64[(off + e0) >> 2];
            add2(acc[j][0], w.x);
            add2(acc[j][1], w.y);
        }
    }

    // Epilogue: LayerNorm over E=256 (64 threads per sample = 2 warps), ReLU, store
    const int warp = tid >> 5;
    const int lane = tid & 31;
    float xv[8][4], s1[8], s2[8];
    #pragma unroll
    for (int j = 0; j < 8; j++) {
        upk2(acc[j][0], xv[j][0], xv[j][1]);
        upk2(acc[j][1], xv[j][2], xv[j][3]);
        s1[j] = xv[j][0] + xv[j][1] + xv[j][2] + xv[j][3];
        s2[j] = xv[j][0] * xv[j][0] + xv[j][1] * xv[j][1]
              + xv[j][2] * xv[j][2] + xv[j][3] * xv[j][3];
    }
    #pragma unroll
    for (int o = 16; o; o >>= 1) {
        #pragma unroll
        for (int j = 0; j < 8; j++) {
            s1[j] += __shfl_xor_sync(0xffffffffu, s1[j], o);
            s2[j] += __shfl_xor_sync(0xffffffffu, s2[j], o);
        }
    }
    if (lane == 0) {
        #pragma unroll
        for (int j = 0; j < 8; j++) { red[warp][j][0] = s1[j]; red[warp][j][1] = s2[j]; }
    }
    __syncthreads();

    float4 g4 = *reinterpret_cast<const float4*>(&gamma[e0]);
    float4 b4 = *reinterpret_cast<const float4*>(&beta[e0]);
    const int pw = warp ^ 1;   // partner warp (same jg)
    #pragma unroll
    for (int j = 0; j < 8; j++) {
        float S1 = s1[j] + red[pw][j][0];
        float S2 = s2[j] + red[pw][j][1];
        float mu = S1 * (1.0f / E_DIM);
        float var = S2 * (1.0f / E_DIM) - mu * mu;
        float rstd = rsqrtf(var + 1e-5f);
        float4 o;
        o.x = fmaxf(0.f, (xv[j][0] - mu) * rstd * g4.x + b4.x);
        o.y = fmaxf(0.f, (xv[j][1] - mu) * rstd * g4.y + b4.y);
        o.z = fmaxf(0.f, (xv[j][2] - mu) * rstd * g4.z + b4.z);
        o.w = fmaxf(0.f, (xv[j][3] - mu) * rstd * g4.w + b4.w);
        *reinterpret_cast<float4*>(&out[(size_t)(b0 + jbase + j) * E_DIM + e0]) = o;
    }
}

// ---------------- launch ----------------
extern "C" void kernel_launch(void* const* d_in, const int* in_sizes, int n_in,
                              void* d_out, int out_size) {
    const float* metadata = (const float*)d_in[0];
    const float* Wd    = (const float*)d_in[1];
    const float* bd    = (const float*)d_in[2];
    const float* Wc    = (const float*)d_in[3];
    const float* bc    = (const float*)d_in[4];
    const float* Wr    = (const float*)d_in[5];
    const float* br    = (const float*)d_in[6];
    const float* emb   = (const float*)d_in[7];
    const float* Wf    = (const float*)d_in[8];
    const float* bf    = (const float*)d_in[9];
    const float* gamma = (const float*)d_in[10];
    const float* beta  = (const float*)d_in[11];
    float* out = (float*)d_out;

    int B = in_sizes[0] / 140;

    int pre_blocks = (E_DIM * I_DIM * 32 + 255) / 256;   // one warp per (e,i)
    precompute_kernel<<<pre_blocks, 256>>>(Wd, bd, Wc, bc, Wr, br, emb, Wf);
    finalize_kernel<<<1, E_DIM>>>(bf);
    main_kernel<<<B / TILE_B, THREADS_MAIN>>>(metadata, gamma, beta, out);
}

// round 2
// speedup vs baseline: 1.1840x; 1.1840x over previous
#include <cuda_runtime.h>
#include <cstdint>

// Problem constants
#define E_DIM 256
#define I_DIM 35
#define K_SCALAR 105          // 3*I scalar features (rows 0..104 of W2T)
#define EMB_ROW0 105          // emb rows: 105 + 4*i + r
#define KROWS 245             // 105 + 35*4
#define TILE_B 32
#define THREADS_MAIN 256

// Scratch (device globals: no allocation allowed)
__device__ __align__(16) float g_W2T[KROWS * E_DIM];     // [row][e] folded weights
__device__ __align__(16) float g_Bsum[I_DIM * E_DIM];    // per-i bias dot partials

// ---------------- f32x2 helpers ----------------
__device__ __forceinline__ void fma2(unsigned long long& d, unsigned long long a, unsigned long long b) {
    asm("fma.rn.f32x2 %0, %1, %2, %0;" : "+l"(d) : "l"(a), "l"(b));
}
__device__ __forceinline__ void add2(unsigned long long& d, unsigned long long a) {
    asm("add.rn.f32x2 %0, %0, %1;" : "+l"(d) : "l"(a));
}
__device__ __forceinline__ unsigned long long pk2(float a, float b) {
    unsigned long long r; asm("mov.b64 %0, {%1, %2};" : "=l"(r) : "f"(a), "f"(b)); return r;
}
__device__ __forceinline__ void upk2(unsigned long long v, float& a, float& b) {
    asm("mov.b64 {%0, %1}, %2;" : "=f"(a), "=f"(b) : "l"(v));
}
__device__ __forceinline__ float dot4(float4 a, float4 b) {
    return a.x * b.x + a.y * b.y + a.z * b.z + a.w * b.w;
}

// ---------------- Precompute: fold Wf with per-feature weight vectors ----------------
// One warp per (e, i). Lane ownership:
//   chunk0 (wf[0:128)):  lanes 0-15 -> depth dot, lanes 16-31 -> cov dot
//   chunk1 (wf[128:256)): lanes 0-15 -> rlen dot, lanes 16-31 -> 4 emb dots
__global__ __launch_bounds__(256)
void precompute_kernel(const float* __restrict__ Wd, const float* __restrict__ bd,
                       const float* __restrict__ Wc, const float* __restrict__ bc,
                       const float* __restrict__ Wr, const float* __restrict__ br,
                       const float* __restrict__ emb, const float* __restrict__ Wf) {
    int gw = (blockIdx.x * blockDim.x + threadIdx.x) >> 5;
    int lane = threadIdx.x & 31;
    if (gw >= E_DIM * I_DIM) return;
    int e = gw / I_DIM;
    int i = gw - e * I_DIM;
    const float* wf = Wf + (size_t)e * (I_DIM * 4 * 64) + (size_t)i * 256;

    const int half = lane >> 4;        // 0: lanes 0-15, 1: lanes 16-31
    const int c = (lane & 15) * 4;

    // chunk 0: features depth (lower) / cov (upper)
    float4 f0 = *reinterpret_cast<const float4*>(wf + lane * 4);
    const float4* w0p = half ? reinterpret_cast<const float4*>(Wc + i * 64 + c)
                             : reinterpret_cast<const float4*>(Wd + i * 64 + c);
    const float4* b0p = half ? reinterpret_cast<const float4*>(bc + i * 64 + c)
                             : reinterpret_cast<const float4*>(bd + i * 64 + c);
    float a0 = dot4(*w0p, f0);
    float pb = dot4(*b0p, f0);

    // chunk 1: rlen (lower) / emb 4 rows (upper)
    float4 f1 = *reinterpret_cast<const float4*>(wf + 128 + lane * 4);
    float a1 = 0.f, pe0 = 0.f, pe1 = 0.f, pe2 = 0.f, pe3 = 0.f;
    if (half == 0) {
        a1 = dot4(*reinterpret_cast<const float4*>(Wr + i * 64 + c), f1);
        pb += dot4(*reinterpret_cast<const float4*>(br + i * 64 + c), f1);
    } else {
        const float* eb = emb + (size_t)(i * 4) * 64 + c;
        pe0 = dot4(*reinterpret_cast<const float4*>(eb), f1);
        pe1 = dot4(*reinterpret_cast<const float4*>(eb + 64), f1);
        pe2 = dot4(*reinterpret_cast<const float4*>(eb + 128), f1);
        pe3 = dot4(*reinterpret_cast<const float4*>(eb + 192), f1);
    }

    // reduce within 16-lane halves (lane0 gets sum of 0-15, lane16 of 16-31)
    #pragma unroll
    for (int o = 8; o; o >>= 1) {
        a0  += __shfl_down_sync(0xffffffffu, a0, o);
        a1  += __shfl_down_sync(0xffffffffu, a1, o);
        pe0 += __shfl_down_sync(0xffffffffu, pe0, o);
        pe1 += __shfl_down_sync(0xffffffffu, pe1, o);
        pe2 += __shfl_down_sync(0xffffffffu, pe2, o);
        pe3 += __shfl_down_sync(0xffffffffu, pe3, o);
    }
    #pragma unroll
    for (int o = 16; o; o >>= 1) pb += __shfl_down_sync(0xffffffffu, pb, o);

    if (lane == 0) {
        g_W2T[(0 * I_DIM + i) * E_DIM + e] = a0;   // depth row
        g_W2T[(2 * I_DIM + i) * E_DIM + e] = a1;   // rlen row
        g_Bsum[i * E_DIM + e] = pb;
    }
    if (lane == 16) {
        g_W2T[(1 * I_DIM + i) * E_DIM + e] = a0;   // cov row
        g_W2T[(EMB_ROW0 + 4 * i + 0) * E_DIM + e] = pe0;
        g_W2T[(EMB_ROW0 + 4 * i + 1) * E_DIM + e] = pe1;
        g_W2T[(EMB_ROW0 + 4 * i + 2) * E_DIM + e] = pe2;
        g_W2T[(EMB_ROW0 + 4 * i + 3) * E_DIM + e] = pe3;
    }
}

// ---------------- Main: out[b,e] = relu(LN(const + X·W2T + emb gathers)) ----------------
// Block: 32 samples x full E=256. Thread: 8 samples x 4 e (two f32x2 accums per sample).
__global__ __launch_bounds__(THREADS_MAIN, 2)
void main_kernel(const float* __restrict__ metadata,
                 const float* __restrict__ bf,
                 const float* __restrict__ gamma,
                 const float* __restrict__ beta,
                 float* __restrict__ out) {
    __shared__ __align__(16) float2 Xs2[TILE_B * 106];   // pre-duplicated {x,x}, k=0..104
    __shared__ int offs[TILE_B * 36];                    // emb row element offsets
    __shared__ float red[8][8][2];                       // [warp][j][{s1,s2}]

    const int tid = threadIdx.x;
    const int b0 = blockIdx.x * TILE_B;

    // Stage X scalars, duplicated for f32x2
    for (int idx = tid; idx < TILE_B * K_SCALAR; idx += THREADS_MAIN) {
        int j = idx / K_SCALAR;
        int k = idx - j * K_SCALAR;
        float v = metadata[(size_t)(b0 + j) * 140 + k];
        Xs2[j * 106 + k] = make_float2(v, v);
    }
    // Stage rt -> W2T row element offsets
    for (int idx = tid; idx < TILE_B * I_DIM; idx += THREADS_MAIN) {
        int j = idx / I_DIM;
        int i = idx - j * I_DIM;
        float v = metadata[(size_t)(b0 + j) * 140 + K_SCALAR + i];
        int ri = (int)v;
        int r = ri >= 0 ? ri : (ri == -1 ? 2 : 3);
        offs[j * 36 + i] = (EMB_ROW0 + 4 * i + r) * E_DIM;
    }

    const int eq = tid & 63;          // 64 e-quads
    const int jg = tid >> 6;          // 4 sample groups of 8
    const int e0 = eq * 4;
    const int jbase = jg * 8;

    // Per-thread constant: bf[e0..3] + sum_i Bsum[i][e0..3]  (overlaps staging)
    float4 cv = *reinterpret_cast<const float4*>(&bf[e0]);
    #pragma unroll 7
    for (int i = 0; i < I_DIM; i++) {
        float4 t = *reinterpret_cast<const float4*>(&g_Bsum[i * E_DIM + e0]);
        cv.x += t.x; cv.y += t.y; cv.z += t.z; cv.w += t.w;
    }
    __syncthreads();

    const ulonglong2* __restrict__ W64 = reinterpret_cast<const ulonglong2*>(g_W2T);

    unsigned long long acc[8][2];
    {
        unsigned long long c_lo = pk2(cv.x, cv.y);
        unsigned long long c_hi = pk2(cv.z, cv.w);
        #pragma unroll
        for (int j = 0; j < 8; j++) { acc[j][0] = c_lo; acc[j][1] = c_hi; }
    }

    // ---- Scalar GEMM: 52 k-pairs with depth-1 W prefetch, then k=104 tail ----
    ulonglong2 w0 = W64[(0 * E_DIM + e0) >> 2];
    ulonglong2 w1 = W64[(1 * E_DIM + e0) >> 2];
    #pragma unroll 2
    for (int kp = 0; kp < 52; kp++) {
        int k = kp * 2;
        int kn0 = (kp < 51) ? (k + 2) : 104;
        int kn1 = (kp < 51) ? (k + 3) : 104;
        ulonglong2 nw0 = W64[(kn0 * E_DIM + e0) >> 2];
        ulonglong2 nw1 = W64[(kn1 * E_DIM + e0) >> 2];
        #pragma unroll
        for (int j = 0; j < 8; j++) {
            ulonglong2 xx = *reinterpret_cast<const ulonglong2*>(&Xs2[(jbase + j) * 106 + k]);
            fma2(acc[j][0], xx.x, w0.x);
            fma2(acc[j][1], xx.x, w0.y);
            fma2(acc[j][0], xx.y, w1.x);
            fma2(acc[j][1], xx.y, w1.y);
        }
        w0 = nw0; w1 = nw1;
    }
    // tail: k = 104 (w0 holds row 104 from last prefetch)
    #pragma unroll
    for (int j = 0; j < 8; j++) {
        unsigned long long xx = *reinterpret_cast<const unsigned long long*>(&Xs2[(jbase + j) * 106 + 104]);
        fma2(acc[j][0], xx, w0.x);
        fma2(acc[j][1], xx, w0.y);
    }

    // ---- Embedding gathers: depth-1 software pipeline over i ----
    {
        ulonglong2 wg[8];
        #pragma unroll
        for (int j = 0; j < 8; j++)
            wg[j] = W64[(offs[(jbase + j) * 36 + 0] + e0) >> 2];
        #pragma unroll 2
        for (int i = 1; i < I_DIM; i++) {
            ulonglong2 wn[8];
            #pragma unroll
            for (int j = 0; j < 8; j++)
                wn[j] = W64[(offs[(jbase + j) * 36 + i] + e0) >> 2];
            #pragma unroll
            for (int j = 0; j < 8; j++) {
                add2(acc[j][0], wg[j].x);
                add2(acc[j][1], wg[j].y);
                wg[j] = wn[j];
            }
        }
        #pragma unroll
        for (int j = 0; j < 8; j++) {
            add2(acc[j][0], wg[j].x);
            add2(acc[j][1], wg[j].y);
        }
    }

    // ---- Epilogue: LayerNorm over E=256 (2 warps per sample-group), ReLU, store ----
    const int warp = tid >> 5;
    const int lane = tid & 31;
    float xv[8][4], s1[8], s2[8];
    #pragma unroll
    for (int j = 0; j < 8; j++) {
        upk2(acc[j][0], xv[j][0], xv[j][1]);
        upk2(acc[j][1], xv[j][2], xv[j][3]);
        s1[j] = xv[j][0] + xv[j][1] + xv[j][2] + xv[j][3];
        s2[j] = xv[j][0] * xv[j][0] + xv[j][1] * xv[j][1]
              + xv[j][2] * xv[j][2] + xv[j][3] * xv[j][3];
    }
    #pragma unroll
    for (int o = 16; o; o >>= 1) {
        #pragma unroll
        for (int j = 0; j < 8; j++) {
            s1[j] += __shfl_xor_sync(0xffffffffu, s1[j], o);
            s2[j] += __shfl_xor_sync(0xffffffffu, s2[j], o);
        }
    }
    if (lane == 0) {
        #pragma unroll
        for (int j = 0; j < 8; j++) { red[warp][j][0] = s1[j]; red[warp][j][1] = s2[j]; }
    }
    __syncthreads();

    float4 g4 = *reinterpret_cast<const float4*>(&gamma[e0]);
    float4 b4 = *reinterpret_cast<const float4*>(&beta[e0]);
    const int pw = warp ^ 1;   // partner warp (same sample group)
    #pragma unroll
    for (int j = 0; j < 8; j++) {
        float S1 = s1[j] + red[pw][j][0];
        float S2 = s2[j] + red[pw][j][1];
        float mu = S1 * (1.0f / E_DIM);
        float var = S2 * (1.0f / E_DIM) - mu * mu;
        float rstd = rsqrtf(var + 1e-5f);
        float4 o;
        o.x = fmaxf(0.f, (xv[j][0] - mu) * rstd * g4.x + b4.x);
        o.y = fmaxf(0.f, (xv[j][1] - mu) * rstd * g4.y + b4.y);
        o.z = fmaxf(0.f, (xv[j][2] - mu) * rstd * g4.z + b4.z);
        o.w = fmaxf(0.f, (xv[j][3] - mu) * rstd * g4.w + b4.w);
        *reinterpret_cast<float4*>(&out[(size_t)(b0 + jbase + j) * E_DIM + e0]) = o;
    }
}

// ---------------- launch ----------------
extern "C" void kernel_launch(void* const* d_in, const int* in_sizes, int n_in,
                              void* d_out, int out_size) {
    const float* metadata = (const float*)d_in[0];
    const float* Wd    = (const float*)d_in[1];
    const float* bd    = (const float*)d_in[2];
    const float* Wc    = (const float*)d_in[3];
    const float* bc    = (const float*)d_in[4];
    const float* Wr    = (const float*)d_in[5];
    const float* br    = (const float*)d_in[6];
    const float* emb   = (const float*)d_in[7];
    const float* Wf    = (const float*)d_in[8];
    const float* bf    = (const float*)d_in[9];
    const float* gamma = (const float*)d_in[10];
    const float* beta  = (const float*)d_in[11];
    float* out = (float*)d_out;

    int B = in_sizes[0] / 140;

    int pre_blocks = (E_DIM * I_DIM * 32 + 255) / 256;   // one warp per (e,i)
    precompute_kernel<<<pre_blocks, 256>>>(Wd, bd, Wc, bc, Wr, br, emb, Wf);
    main_kernel<<<B / TILE_B, THREADS_MAIN>>>(metadata, bf, gamma, beta, out);
}

// round 4
// speedup vs baseline: 1.7008x; 1.4365x over previous
#include <cuda_runtime.h>
#include <cuda_bf16.h>
#include <cstdint>

// ---------------- problem constants ----------------
#define E_DIM 256
#define I_DIM 35
#define M_TILE 128
#define THREADS 512

// ---------------- smem layout (bytes) ----------------
#define SM_CONST  0                        // float[256]
#define SM_GAMMA  1024
#define SM_BETA   2048
#define SM_SRED   3072                     // float2[128][4] = 4096B
#define SM_AH     8192                     // 4 chunks x 16384B (128m x 64k bf16, swizzled)
#define SM_AL     (SM_AH + 65536)
#define SM_W      (SM_AL + 65536)          // 2 buffers x 32768B (256e x 64k bf16, swizzled)
#define SMEM_TOTAL (SM_W + 65536)          // 204800

// ---------------- device scratch ----------------
__device__ __align__(16) __nv_bfloat16 g_Wh[4 * 16384];   // [chunk][e][k] swizzled, hi split
__device__ __align__(16) __nv_bfloat16 g_Wl[4 * 16384];   // lo split
__device__ __align__(16) float g_Bsum[I_DIM * E_DIM];     // exact fp32 bias partials

// ---------------- helpers ----------------
__device__ __forceinline__ uint32_t smem_u32(const void* p) {
    uint32_t a; asm("{ .reg .u64 t; cvta.to.shared.u64 t, %1; cvt.u32.u64 %0, t; }" : "=r"(a) : "l"(p));
    return a;
}
__device__ __forceinline__ uint32_t swz(uint32_t off) { return off ^ ((off >> 3) & 0x70); }
__device__ __forceinline__ float dot4(float4 a, float4 b) {
    return a.x * b.x + a.y * b.y + a.z * b.z + a.w * b.w;
}
__device__ __forceinline__ void ldsm4(uint32_t (&r)[4], uint32_t addr) {
    asm volatile("ldmatrix.sync.aligned.m8n8.x4.shared.b16 {%0,%1,%2,%3}, [%4];"
                 : "=r"(r[0]), "=r"(r[1]), "=r"(r[2]), "=r"(r[3]) : "r"(addr));
}
__device__ __forceinline__ void mma_bf16(float (&c)[4], const uint32_t (&a)[4], uint32_t b0, uint32_t b1) {
    asm volatile("mma.sync.aligned.m16n8k16.row.col.f32.bf16.bf16.f32 "
                 "{%0,%1,%2,%3}, {%4,%5,%6,%7}, {%8,%9}, {%0,%1,%2,%3};"
                 : "+f"(c[0]), "+f"(c[1]), "+f"(c[2]), "+f"(c[3])
                 : "r"(a[0]), "r"(a[1]), "r"(a[2]), "r"(a[3]), "r"(b0), "r"(b1));
}
#define CP_ASYNC16(dst, src) \
    asm volatile("cp.async.cg.shared.global [%0], [%1], 16;" :: "r"(dst), "l"(src))
#define CP_COMMIT() asm volatile("cp.async.commit_group;" ::: "memory")
#define CP_WAIT(n)  asm volatile("cp.async.wait_group %0;" :: "n"(n) : "memory")

// ---------------- precompute: fold Wf, emit bf16-split swizzled W [e][k] ----------------
__device__ __forceinline__ void store_w(int k, int e, float v) {
    __nv_bfloat16 hi = __float2bfloat16(v);
    __nv_bfloat16 lo = __float2bfloat16(v - __bfloat162float(hi));
    int chunk = k >> 6;
    uint32_t sw = swz((uint32_t)(e * 128 + (k & 63) * 2));
    *reinterpret_cast<__nv_bfloat16*>(reinterpret_cast<char*>(g_Wh) + chunk * 32768 + sw) = hi;
    *reinterpret_cast<__nv_bfloat16*>(reinterpret_cast<char*>(g_Wl) + chunk * 32768 + sw) = lo;
}

__global__ __launch_bounds__(256)
void precompute_kernel(const float* __restrict__ Wd, const float* __restrict__ bd,
                       const float* __restrict__ Wc, const float* __restrict__ bc,
                       const float* __restrict__ Wr, const float* __restrict__ br,
                       const float* __restrict__ emb, const float* __restrict__ Wf) {
    if (blockIdx.x == 0) {                 // zero-pad rows k = 245..255
        int e = threadIdx.x;
        for (int k = 245; k < 256; k++) store_w(k, e, 0.0f);
    }

    int gw = (blockIdx.x * blockDim.x + threadIdx.x) >> 5;
    int lane = threadIdx.x & 31;
    if (gw >= E_DIM * I_DIM) return;
    int e = gw / I_DIM;
    int i = gw - e * I_DIM;
    const float* wf = Wf + (size_t)e * (I_DIM * 256) + (size_t)i * 256;

    const int half = lane >> 4;
    const int c = (lane & 15) * 4;

    float4 f0 = *reinterpret_cast<const float4*>(wf + lane * 4);
    const float4* w0p = half ? reinterpret_cast<const float4*>(Wc + i * 64 + c)
                             : reinterpret_cast<const float4*>(Wd + i * 64 + c);
    const float4* b0p = half ? reinterpret_cast<const float4*>(bc + i * 64 + c)
                             : reinterpret_cast<const float4*>(bd + i * 64 + c);
    float a0 = dot4(*w0p, f0);
    float pb = dot4(*b0p, f0);

    float4 f1 = *reinterpret_cast<const float4*>(wf + 128 + lane * 4);
    float a1 = 0.f, pe0 = 0.f, pe1 = 0.f, pe2 = 0.f, pe3 = 0.f;
    if (half == 0) {
        a1 = dot4(*reinterpret_cast<const float4*>(Wr + i * 64 + c), f1);
        pb += dot4(*reinterpret_cast<const float4*>(br + i * 64 + c), f1);
    } else {
        const float* eb = emb + (size_t)(i * 4) * 64 + c;
        pe0 = dot4(*reinterpret_cast<const float4*>(eb), f1);
        pe1 = dot4(*reinterpret_cast<const float4*>(eb + 64), f1);
        pe2 = dot4(*reinterpret_cast<const float4*>(eb + 128), f1);
        pe3 = dot4(*reinterpret_cast<const float4*>(eb + 192), f1);
    }

    #pragma unroll
    for (int o = 8; o; o >>= 1) {
        a0  += __shfl_down_sync(0xffffffffu, a0, o);
        a1  += __shfl_down_sync(0xffffffffu, a1, o);
        pe0 += __shfl_down_sync(0xffffffffu, pe0, o);
        pe1 += __shfl_down_sync(0xffffffffu, pe1, o);
        pe2 += __shfl_down_sync(0xffffffffu, pe2, o);
        pe3 += __shfl_down_sync(0xffffffffu, pe3, o);
    }
    #pragma unroll
    for (int o = 16; o; o >>= 1) pb += __shfl_down_sync(0xffffffffu, pb, o);

    if (lane == 0) {
        store_w(i, e, a0);            // depth
        store_w(70 + i, e, a1);       // rlen
        g_Bsum[i * E_DIM + e] = pb;
    }
    if (lane == 16) {
        store_w(35 + i, e, a0);       // cov
        store_w(105 + 4 * i + 0, e, pe0);
        store_w(105 + 4 * i + 1, e, pe1);
        store_w(105 + 4 * i + 2, e, pe2);
        store_w(105 + 4 * i + 3, e, pe3);
    }
}

// ---------------- main: HMMA GEMM + fused LayerNorm/ReLU ----------------
__global__ __launch_bounds__(THREADS, 1)
void main_kernel(const float* __restrict__ metadata,
                 const float* __restrict__ bf,
                 const float* __restrict__ gamma,
                 const float* __restrict__ beta,
                 float* __restrict__ out) {
    extern __shared__ __align__(1024) char sm[];
    const uint32_t sbase = smem_u32(sm);
    const int tid = threadIdx.x;
    const int wid = tid >> 5;
    const int lane = tid & 31;
    const int b0 = blockIdx.x * M_TILE;

    const int nwarp = wid & 3;            // n_base = nwarp*64
    const int mwarp = wid >> 2;           // m_base = mwarp*32
    const int n_base = nwarp * 64;
    const int m_base = mwarp * 32;

    // zero A (hi+lo, 128KB)
    {
        uint4 z = make_uint4(0, 0, 0, 0);
        uint4* p = reinterpret_cast<uint4*>(sm + SM_AH);
        #pragma unroll
        for (int it = 0; it < 16; it++) p[tid + it * THREADS] = z;
    }
    // const / gamma / beta
    if (tid < E_DIM) {
        int e = tid;
        float s = bf[e];
        #pragma unroll 7
        for (int i = 0; i < I_DIM; i++) s += g_Bsum[i * E_DIM + e];
        *reinterpret_cast<float*>(sm + SM_CONST + e * 4) = s;
        *reinterpret_cast<float*>(sm + SM_GAMMA + e * 4) = gamma[e];
        *reinterpret_cast<float*>(sm + SM_BETA + e * 4) = beta[e];
    }
    __syncthreads();

    // stage A from metadata: k<105 scalars (bf16 split), k>=105 -> one-hot
    for (int idx = tid; idx < M_TILE * 140; idx += THREADS) {
        int m = idx / 140;
        int k = idx - m * 140;
        float v = metadata[(size_t)(b0 + m) * 140 + k];
        if (k < 105) {
            __nv_bfloat16 hi = __float2bfloat16(v);
            __nv_bfloat16 lo = __float2bfloat16(v - __bfloat162float(hi));
            int chunk = k >> 6;
            uint32_t sw = swz((uint32_t)(m * 128 + (k & 63) * 2));
            *reinterpret_cast<__nv_bfloat16*>(sm + SM_AH + chunk * 16384 + sw) = hi;
            *reinterpret_cast<__nv_bfloat16*>(sm + SM_AL + chunk * 16384 + sw) = lo;
        } else {
            int i = k - 105;
            int ri = (int)v;
            int r = ri >= 0 ? ri : (ri == -1 ? 2 : 3);
            int kk = 105 + 4 * i + r;
            uint32_t sw = swz((uint32_t)(m * 128 + (kk & 63) * 2));
            *reinterpret_cast<__nv_bfloat16*>(sm + SM_AH + (kk >> 6) * 16384 + sw) = __float2bfloat16(1.0f);
        }
    }

    // ---- mainloop: 8 passes (Wh0, Wl0, Wh1, Wl1, ...) with cp.async double buffer ----
    float acc[2][8][4];
    #pragma unroll
    for (int mt = 0; mt < 2; mt++)
        #pragma unroll
        for (int nt = 0; nt < 8; nt++)
            #pragma unroll
            for (int q = 0; q < 4; q++) acc[mt][nt][q] = 0.f;

    const int r8 = lane & 7, j = lane >> 3;
    const uint32_t ka = (j >> 1) * 16;        // A k-byte offset
    const uint32_t kb = (j & 1) * 16;         // B k-byte offset
    uint32_t aRowB[2], bRowB[4];
    #pragma unroll
    for (int mt = 0; mt < 2; mt++) aRowB[mt] = (uint32_t)(m_base + mt * 16 + (j & 1) * 8 + r8) * 128;
    #pragma unroll
    for (int np = 0; np < 4; np++) bRowB[np] = (uint32_t)(n_base + np * 16 + (j >> 1) * 8 + r8) * 128;

    // issue W pass 0
    {
        const char* src = reinterpret_cast<const char*>(g_Wh);
        #pragma unroll
        for (int it = 0; it < 4; it++) {
            uint32_t off = tid * 16 + it * 8192;
            CP_ASYNC16(sbase + SM_W + off, src + off);
        }
        CP_COMMIT();
    }

    for (int p = 0; p < 8; p++) {
        const uint32_t wbuf = sbase + SM_W + (p & 1) * 32768;
        const bool hiW = (p & 1) == 0;
        const int chunk = p >> 1;

        if (p < 7) {
            int pn = p + 1;
            const char* src = reinterpret_cast<const char*>((pn & 1) == 0 ? g_Wh : g_Wl) + (pn >> 1) * 32768;
            uint32_t dbuf = sbase + SM_W + (pn & 1) * 32768;
            #pragma unroll
            for (int it = 0; it < 4; it++) {
                uint32_t off = tid * 16 + it * 8192;
                CP_ASYNC16(dbuf + off, src + off);
            }
            CP_COMMIT();
            CP_WAIT(1);
        } else {
            CP_WAIT(0);
        }
        __syncthreads();   // W buf ready; A staged (first iter)

        const uint32_t ahBase = sbase + SM_AH + chunk * 16384;
        const uint32_t alBase = sbase + SM_AL + chunk * 16384;

        #pragma unroll
        for (int kk = 0; kk < 4; kk++) {
            uint32_t ah[2][4], al[2][4];
            #pragma unroll
            for (int mt = 0; mt < 2; mt++)
                ldsm4(ah[mt], ahBase + swz(aRowB[mt] + kk * 32 + ka));
            if (hiW) {
                #pragma unroll
                for (int mt = 0; mt < 2; mt++)
                    ldsm4(al[mt], alBase + swz(aRowB[mt] + kk * 32 + ka));
            }
            #pragma unroll
            for (int np = 0; np < 4; np++) {
                uint32_t b[4];
                ldsm4(b, wbuf + swz(bRowB[np] + kk * 32 + kb));
                #pragma unroll
                for (int mt = 0; mt < 2; mt++) {
                    mma_bf16(acc[mt][np * 2 + 0], ah[mt], b[0], b[1]);
                    mma_bf16(acc[mt][np * 2 + 1], ah[mt], b[2], b[3]);
                }
                if (hiW) {
                    #pragma unroll
                    for (int mt = 0; mt < 2; mt++) {
                        mma_bf16(acc[mt][np * 2 + 0], al[mt], b[0], b[1]);
                        mma_bf16(acc[mt][np * 2 + 1], al[mt], b[2], b[3]);
                    }
                }
            }
        }
        __syncthreads();   // compute done before buffer reuse
    }

    // ---- epilogue: add const, per-row LayerNorm + ReLU, store ----
    const float* cst = reinterpret_cast<const float*>(sm + SM_CONST);
    const float* gmm = reinterpret_cast<const float*>(sm + SM_GAMMA);
    const float* bta = reinterpret_cast<const float*>(sm + SM_BETA);
    float2* sred = reinterpret_cast<float2*>(sm + SM_SRED);
    const int g = lane >> 2, t = lane & 3;

    float s1[4] = {0, 0, 0, 0}, s2[4] = {0, 0, 0, 0};   // q = mt*2 + h
    #pragma unroll
    for (int mt = 0; mt < 2; mt++)
        #pragma unroll
        for (int nt = 0; nt < 8; nt++) {
            int col0 = n_base + nt * 8 + t * 2;
            float c0 = cst[col0], c1 = cst[col0 + 1];
            #pragma unroll
            for (int h = 0; h < 2; h++) {
                float v0 = acc[mt][nt][h * 2 + 0] + c0;
                float v1 = acc[mt][nt][h * 2 + 1] + c1;
                acc[mt][nt][h * 2 + 0] = v0;
                acc[mt][nt][h * 2 + 1] = v1;
                s1[mt * 2 + h] += v0 + v1;
                s2[mt * 2 + h] += v0 * v0 + v1 * v1;
            }
        }
    #pragma unroll
    for (int q = 0; q < 4; q++) {
        s1[q] += __shfl_xor_sync(0xffffffffu, s1[q], 1);
        s1[q] += __shfl_xor_sync(0xffffffffu, s1[q], 2);
        s2[q] += __shfl_xor_sync(0xffffffffu, s2[q], 1);
        s2[q] += __shfl_xor_sync(0xffffffffu, s2[q], 2);
    }
    {
        int rowq = m_base + (t >> 1) * 16 + (t & 1) * 8 + g;
        sred[rowq * 4 + nwarp] = make_float2(s1[t], s2[t]);
    }
    __syncthreads();

    float mu[4], rs[4];
    #pragma unroll
    for (int q = 0; q < 4; q++) {
        int row = m_base + (q >> 1) * 16 + (q & 1) * 8 + g;
        float2 p0 = sred[row * 4 + 0], p1 = sred[row * 4 + 1];
        float2 p2 = sred[row * 4 + 2], p3 = sred[row * 4 + 3];
        float S1 = p0.x + p1.x + p2.x + p3.x;
        float S2 = p0.y + p1.y + p2.y + p3.y;
        mu[q] = S1 * (1.0f / E_DIM);
        float var = S2 * (1.0f / E_DIM) - mu[q] * mu[q];
        rs[q] = rsqrtf(var + 1e-5f);
    }

    #pragma unroll
    for (int mt = 0; mt < 2; mt++)
        #pragma unroll
        for (int h = 0; h < 2; h++) {
            int q = mt * 2 + h;
            size_t grow = (size_t)(b0 + m_base + mt * 16 + h * 8 + g);
            #pragma unroll
            for (int nt = 0; nt < 8; nt++) {
                int col0 = n_base + nt * 8 + t * 2;
                float y0 = fmaxf(0.f, (acc[mt][nt][h * 2 + 0] - mu[q]) * rs[q] * gmm[col0] + bta[col0]);
                float y1 = fmaxf(0.f, (acc[mt][nt][h * 2 + 1] - mu[q]) * rs[q] * gmm[col0 + 1] + bta[col0 + 1]);
                *reinterpret_cast<float2*>(out + grow * E_DIM + col0) = make_float2(y0, y1);
            }
        }
}

// ---------------- launch ----------------
extern "C" void kernel_launch(void* const* d_in, const int* in_sizes, int n_in,
                              void* d_out, int out_size) {
    const float* metadata = (const float*)d_in[0];
    const float* Wd    = (const float*)d_in[1];
    const float* bd    = (const float*)d_in[2];
    const float* Wc    = (const float*)d_in[3];
    const float* bc    = (const float*)d_in[4];
    const float* Wr    = (const float*)d_in[5];
    const float* br    = (const float*)d_in[6];
    const float* emb   = (const float*)d_in[7];
    const float* Wf    = (const float*)d_in[8];
    const float* bf    = (const float*)d_in[9];
    const float* gamma = (const float*)d_in[10];
    const float* beta  = (const float*)d_in[11];
    float* out = (float*)d_out;

    int B = in_sizes[0] / 140;

    static bool attr_set = false;
    if (!attr_set) {
        cudaFuncSetAttribute(main_kernel, cudaFuncAttributeMaxDynamicSharedMemorySize, SMEM_TOTAL);
        attr_set = true;
    }

    int pre_blocks = (E_DIM * I_DIM * 32 + 255) / 256;
    precompute_kernel<<<pre_blocks, 256>>>(Wd, bd, Wc, bc, Wr, br, emb, Wf);
    main_kernel<<<B / M_TILE, THREADS, SMEM_TOTAL>>>(metadata, bf, gamma, beta, out);
}